// round 1
// baseline (speedup 1.0000x reference)
#include <cuda_runtime.h>
#include <math.h>
#include <float.h>
#include <stdint.h>

#define BATCH 32
#define NROWS 16384
#define DDIM 64
#define CHUNKS 16
#define RPC (NROWS/CHUNKS)     /* 1024 rows per chunk */
#define TRI 2080
#define TOTAL (BATCH*TRI)      /* 66560 */
#define LAMBDA_REG 0.01f
#define SP 68                  /* padded smem row stride (floats) */

__device__ float g_Spart[CHUNKS*BATCH*DDIM*DDIM];  /* 8 MB partial Gram */
__device__ float g_Csum[CHUNKS*BATCH*DDIM];
__device__ float g_bufA[TOTAL];
__device__ float g_bufB[TOTAL];

__device__ __forceinline__ unsigned tf32r(float v){
    unsigned u;
    asm("cvt.rna.tf32.f32 %0, %1;" : "=r"(u) : "f"(v));
    return u;
}

__device__ __forceinline__ void mma8(float c[4],
                                     unsigned a0, unsigned a1, unsigned a2, unsigned a3,
                                     unsigned b0, unsigned b1){
    asm volatile("mma.sync.aligned.m16n8k8.row.col.f32.tf32.tf32.f32 "
        "{%0,%1,%2,%3},{%4,%5,%6,%7},{%8,%9},{%0,%1,%2,%3};"
        : "+f"(c[0]),"+f"(c[1]),"+f"(c[2]),"+f"(c[3])
        : "r"(a0),"r"(a1),"r"(a2),"r"(a3),"r"(b0),"r"(b1));
}

/* ------------------------------------------------------------------ */
/* Kernel 1: per-(chunk,batch) partial Gram matrix S += X^T X via tf32
   MMA, plus per-column sums for the mean.                            */
/* ------------------------------------------------------------------ */
__global__ __launch_bounds__(256) void cov_partial(const float* __restrict__ x){
    __shared__ float Xs[64][SP];
    __shared__ float red[16][64];

    const int chunk = blockIdx.x;
    const int b     = blockIdx.y;
    const int tid   = threadIdx.x;
    const int wid   = tid >> 5;
    const int lane  = tid & 31;
    const int m0 = (wid >> 1) * 16;    /* warp covers rows m0..m0+15   */
    const int n0 = (wid & 1) * 32;     /* warp covers cols n0..n0+31   */
    const int lg = lane >> 2;          /* 0..7 */
    const int lc = lane & 3;           /* 0..3 */

    float acc[4][4];
    #pragma unroll
    for (int i = 0; i < 4; i++)
        #pragma unroll
        for (int j = 0; j < 4; j++) acc[i][j] = 0.f;

    float cs0 = 0.f, cs1 = 0.f, cs2 = 0.f, cs3 = 0.f;
    const int r  = tid >> 4;   /* 0..15 staging row group */
    const int cg = tid & 15;   /* 0..15 staging col group (4 floats) */

    const float* xb = x + ((size_t)b * NROWS + (size_t)chunk * RPC) * DDIM;

    for (int t = 0; t < RPC/64; t++){
        const float* src = xb + (size_t)t * 64 * DDIM;
        /* stage 64x64 tile, convert to tf32-rounded, accumulate col sums */
        #pragma unroll
        for (int i = 0; i < 4; i++){
            int row = r + 16*i;
            float4 v = *(const float4*)(src + row*DDIM + cg*4);
            cs0 += v.x; cs1 += v.y; cs2 += v.z; cs3 += v.w;
            float4 w;
            w.x = __uint_as_float(tf32r(v.x));
            w.y = __uint_as_float(tf32r(v.y));
            w.z = __uint_as_float(tf32r(v.z));
            w.w = __uint_as_float(tf32r(v.w));
            *(float4*)&Xs[row][cg*4] = w;
        }
        __syncthreads();

        #pragma unroll
        for (int kk = 0; kk < 64; kk += 8){
            unsigned a0 = __float_as_uint(Xs[kk   + lc][m0     + lg]);
            unsigned a1 = __float_as_uint(Xs[kk   + lc][m0 + 8 + lg]);
            unsigned a2 = __float_as_uint(Xs[kk+4 + lc][m0     + lg]);
            unsigned a3 = __float_as_uint(Xs[kk+4 + lc][m0 + 8 + lg]);
            #pragma unroll
            for (int nt = 0; nt < 4; nt++){
                int nb = n0 + nt*8;
                unsigned b0 = __float_as_uint(Xs[kk   + lc][nb + lg]);
                unsigned b1 = __float_as_uint(Xs[kk+4 + lc][nb + lg]);
                mma8(acc[nt], a0, a1, a2, a3, b0, b1);
            }
        }
        __syncthreads();
    }

    /* write partial Gram */
    const size_t base = (size_t)(chunk*BATCH + b) * 4096;
    const int row0 = m0 + lg;
    #pragma unroll
    for (int nt = 0; nt < 4; nt++){
        int col0 = n0 + nt*8 + lc*2;
        g_Spart[base + (size_t)row0*64 + col0]       = acc[nt][0];
        g_Spart[base + (size_t)row0*64 + col0 + 1]   = acc[nt][1];
        g_Spart[base + (size_t)(row0+8)*64 + col0]   = acc[nt][2];
        g_Spart[base + (size_t)(row0+8)*64 + col0+1] = acc[nt][3];
    }

    /* column-sum reduction across the 16 row-groups */
    red[r][cg*4+0] = cs0;
    red[r][cg*4+1] = cs1;
    red[r][cg*4+2] = cs2;
    red[r][cg*4+3] = cs3;
    __syncthreads();
    if (tid < 64){
        float s = 0.f;
        #pragma unroll
        for (int q = 0; q < 16; q++) s += red[q][tid];
        g_Csum[(chunk*BATCH + b)*64 + tid] = s;
    }
}

/* ------------------------------------------------------------------ */
/* Kernel 2: reduce chunk partials, mean-correct, +lambda*I, emit the
   2080 upper-tri entries per batch into g_bufA.                      */
/* ------------------------------------------------------------------ */
__global__ __launch_bounds__(128) void cov_finalize(void){
    __shared__ float mu[64];
    const int b = blockIdx.x;
    const int tid = threadIdx.x;

    if (tid < 64){
        float s = 0.f;
        #pragma unroll
        for (int c = 0; c < CHUNKS; c++) s += g_Csum[(c*BATCH + b)*64 + tid];
        mu[tid] = s * (1.f / (float)NROWS);
    }
    __syncthreads();

    for (int t = tid; t < TRI; t += 128){
        /* invert linear tri index -> (i, j), i <= j */
        int i = (int)((2.f*DDIM + 1.f - sqrtf((2.f*DDIM+1.f)*(2.f*DDIM+1.f) - 8.f*(float)t)) * 0.5f);
        if (i < 0) i = 0;
        if (i > DDIM-1) i = DDIM-1;
        while (i > 0 && (i*DDIM - (i*(i-1))/2) > t) i--;
        while (((i+1)*DDIM - ((i+1)*i)/2) <= t) i++;
        int off = i*DDIM - (i*(i-1))/2;
        int j = i + (t - off);

        float s = 0.f;
        #pragma unroll
        for (int c = 0; c < CHUNKS; c++)
            s += g_Spart[(size_t)(c*BATCH + b)*4096 + (size_t)i*64 + j];

        float cov = (s - (float)NROWS * mu[i] * mu[j]) * (1.f / (float)(NROWS-1));
        if (i == j) cov += LAMBDA_REG;
        g_bufA[b*TRI + t] = cov;
    }
}

/* ------------------------------------------------------------------ */
/* Kernel 3: per-batch bitonic sort of 2080 entries (pad to 4096).    */
/* ------------------------------------------------------------------ */
__global__ __launch_bounds__(512) void sort_block(void){
    __shared__ float s[4096];
    const int b = blockIdx.x;
    const int tid = threadIdx.x;

    for (int i = tid; i < 4096; i += 512)
        s[i] = (i < TRI) ? g_bufA[b*TRI + i] : INFINITY;
    __syncthreads();

    for (int k = 2; k <= 4096; k <<= 1){
        for (int j = k >> 1; j > 0; j >>= 1){
            for (int i = tid; i < 4096; i += 512){
                int ixj = i ^ j;
                if (ixj > i){
                    float a = s[i], c = s[ixj];
                    bool up = ((i & k) == 0);
                    if (up ? (a > c) : (a < c)){ s[i] = c; s[ixj] = a; }
                }
            }
            __syncthreads();
        }
    }
    for (int i = tid; i < TRI; i += 512) g_bufA[b*TRI + i] = s[i];
}

/* ------------------------------------------------------------------ */
/* Kernel 4: merge round — merge adjacent sorted runs of length L via
   per-element binary-search rank (stable).                           */
/* ------------------------------------------------------------------ */
__global__ __launch_bounds__(256) void merge_round(int L, int mode, float* final_out){
    const float* src; float* dst;
    if      (mode == 0){ src = g_bufA; dst = g_bufB; }
    else if (mode == 1){ src = g_bufB; dst = g_bufA; }
    else               { src = g_bufA; dst = final_out; }

    int gid = blockIdx.x * blockDim.x + threadIdx.x;
    if (gid >= TOTAL) return;

    int pair  = gid / (2*L);
    int base  = pair * 2 * L;
    int local = gid - base;
    float v = src[gid];
    int rank;
    if (local < L){
        const float* Brun = src + base + L;
        int lo = 0, hi = L;
        while (lo < hi){ int mid = (lo + hi) >> 1; if (Brun[mid] <  v) lo = mid+1; else hi = mid; }
        rank = local + lo;
    } else {
        const float* Arun = src + base;
        int ib = local - L;
        int lo = 0, hi = L;
        while (lo < hi){ int mid = (lo + hi) >> 1; if (Arun[mid] <= v) lo = mid+1; else hi = mid; }
        rank = ib + lo;
    }
    dst[base + rank] = v;
}

/* ------------------------------------------------------------------ */
extern "C" void kernel_launch(void* const* d_in, const int* in_sizes, int n_in,
                              void* d_out, int out_size){
    const float* x = (const float*)d_in[0];
    float* out = (float*)d_out;

    dim3 gcov(CHUNKS, BATCH);
    cov_partial<<<gcov, 256>>>(x);
    cov_finalize<<<BATCH, 128>>>();
    sort_block<<<BATCH, 512>>>();

    int mgrid = (TOTAL + 255) / 256;
    merge_round<<<mgrid, 256>>>(TRI,      0, out);  /* A -> B : runs 2080  */
    merge_round<<<mgrid, 256>>>(TRI*2,    1, out);  /* B -> A : runs 4160  */
    merge_round<<<mgrid, 256>>>(TRI*4,    0, out);  /* A -> B : runs 8320  */
    merge_round<<<mgrid, 256>>>(TRI*8,    1, out);  /* B -> A : runs 16640 */
    merge_round<<<mgrid, 256>>>(TRI*16,   2, out);  /* A -> d_out : 33280  */
}

// round 3
// speedup vs baseline: 1.2909x; 1.2909x over previous
#include <cuda_runtime.h>
#include <math.h>
#include <float.h>
#include <stdint.h>

#define BATCH 32
#define NROWS 16384
#define DDIM 64
#define CHUNKS 16
#define RPC (NROWS/CHUNKS)     /* 1024 rows per chunk */
#define NT (RPC/64)            /* 16 tiles of 64 rows */
#define TRI 2080
#define TOTAL (BATCH*TRI)      /* 66560 */
#define LAMBDA_REG 0.01f
#define SP 68                  /* padded smem row stride (floats) */

__device__ float g_Spart[CHUNKS*BATCH*DDIM*DDIM];  /* 8 MB partial Gram */
__device__ float g_Csum[CHUNKS*BATCH*DDIM];
__device__ float g_bufA[TOTAL];
__device__ float g_bufB[TOTAL];

__device__ __forceinline__ void mma8(float c[4],
                                     unsigned a0, unsigned a1, unsigned a2, unsigned a3,
                                     unsigned b0, unsigned b1){
    asm volatile("mma.sync.aligned.m16n8k8.row.col.f32.tf32.tf32.f32 "
        "{%0,%1,%2,%3},{%4,%5,%6,%7},{%8,%9},{%0,%1,%2,%3};"
        : "+f"(c[0]),"+f"(c[1]),"+f"(c[2]),"+f"(c[3])
        : "r"(a0),"r"(a1),"r"(a2),"r"(a3),"r"(b0),"r"(b1));
}

__device__ __forceinline__ void cp16(uint32_t smem_dst, const void* gsrc){
    asm volatile("cp.async.cg.shared.global [%0], [%1], 16;\n"
                 :: "r"(smem_dst), "l"(gsrc));
}

/* ------------------------------------------------------------------ */
/* Kernel 1: per-(chunk,batch) partial Gram via tf32 MMA.
   cp.async double-buffered; 8 warps = 4 quadrants (32x32) x 2 k-halves;
   raw fp32 bits fed to HMMA.TF32 (HW truncates mantissa).             */
/* ------------------------------------------------------------------ */
__global__ __launch_bounds__(256) void cov_partial(const float* __restrict__ x){
    __shared__ float Xs[2][64][SP];     /* 2 x 17408 B */
    __shared__ float red[4][64];

    const int chunk = blockIdx.x;
    const int b     = blockIdx.y;
    const int tid   = threadIdx.x;
    const int wid   = tid >> 5;
    const int lane  = tid & 31;
    const int khalf = wid >> 2;            /* 0/1: k-range 0-31 / 32-63 */
    const int quad  = wid & 3;             /* output quadrant           */
    const int m0 = (quad >> 1) * 32;
    const int n0 = (quad & 1) * 32;
    const int lg = lane >> 2;              /* 0..7 */
    const int lc = lane & 3;               /* 0..3 */

    float acc[2][4][4];
    #pragma unroll
    for (int mt = 0; mt < 2; mt++)
        #pragma unroll
        for (int nt = 0; nt < 4; nt++)
            #pragma unroll
            for (int v = 0; v < 4; v++) acc[mt][nt][v] = 0.f;

    /* staging: thread copies 4 x 16B; rows r, r+16, r+32, r+48 */
    const int sr = tid >> 4;               /* 0..15 */
    const int sc = tid & 15;               /* 0..15 (float4 col) */
    const float* xb = x + ((size_t)b * NROWS + (size_t)chunk * RPC) * DDIM;

    /* colsum: thread owns column csC, rows csQ*16..+15 */
    const int csQ = tid >> 6;              /* 0..3 */
    const int csC = tid & 63;
    float csum = 0.f;

    /* prologue: prefetch tile 0 into buf 0 */
    {
        const float* src = xb;
        #pragma unroll
        for (int i = 0; i < 4; i++){
            int row = sr + 16*i;
            uint32_t dst = (uint32_t)__cvta_generic_to_shared(&Xs[0][row][sc*4]);
            cp16(dst, src + (size_t)row*DDIM + sc*4);
        }
        asm volatile("cp.async.commit_group;\n");
    }

    for (int t = 0; t < NT; t++){
        if (t + 1 < NT){
            const float* src = xb + (size_t)(t+1) * 64 * DDIM;
            int buf = (t+1) & 1;
            #pragma unroll
            for (int i = 0; i < 4; i++){
                int row = sr + 16*i;
                uint32_t dst = (uint32_t)__cvta_generic_to_shared(&Xs[buf][row][sc*4]);
                cp16(dst, src + (size_t)row*DDIM + sc*4);
            }
            asm volatile("cp.async.commit_group;\n");
            asm volatile("cp.async.wait_group 1;\n");
        } else {
            asm volatile("cp.async.wait_group 0;\n");
        }
        __syncthreads();

        const int cb = t & 1;

        /* column sums (raw fp32, exact) */
        #pragma unroll
        for (int k = 0; k < 16; k++)
            csum += Xs[cb][csQ*16 + k][csC];

        /* MMA over this warp's k-half */
        #pragma unroll
        for (int s = 0; s < 4; s++){
            const int kk = khalf*32 + s*8;
            unsigned a[2][4];
            #pragma unroll
            for (int mt = 0; mt < 2; mt++){
                int m = m0 + mt*16;
                a[mt][0] = __float_as_uint(Xs[cb][kk   + lc][m     + lg]);
                a[mt][1] = __float_as_uint(Xs[cb][kk   + lc][m + 8 + lg]);
                a[mt][2] = __float_as_uint(Xs[cb][kk+4 + lc][m     + lg]);
                a[mt][3] = __float_as_uint(Xs[cb][kk+4 + lc][m + 8 + lg]);
            }
            unsigned bf[4][2];
            #pragma unroll
            for (int nt = 0; nt < 4; nt++){
                int nb = n0 + nt*8;
                bf[nt][0] = __float_as_uint(Xs[cb][kk   + lc][nb + lg]);
                bf[nt][1] = __float_as_uint(Xs[cb][kk+4 + lc][nb + lg]);
            }
            #pragma unroll
            for (int mt = 0; mt < 2; mt++)
                #pragma unroll
                for (int nt = 0; nt < 4; nt++)
                    mma8(acc[mt][nt], a[mt][0], a[mt][1], a[mt][2], a[mt][3],
                         bf[nt][0], bf[nt][1]);
        }
        __syncthreads();
    }

    /* k-half 1 warps spill partial accumulators into (now free) buf 0 */
    red[csQ][csC] = csum;
    if (khalf == 1){
        float* sc2 = &Xs[0][0][0] + quad * 1056;   /* 32x33 padded */
        #pragma unroll
        for (int mt = 0; mt < 2; mt++)
            #pragma unroll
            for (int nt = 0; nt < 4; nt++){
                int rr = mt*16 + lg;
                int cc = nt*8 + lc*2;
                sc2[rr*33 + cc]       = acc[mt][nt][0];
                sc2[rr*33 + cc + 1]   = acc[mt][nt][1];
                sc2[(rr+8)*33 + cc]   = acc[mt][nt][2];
                sc2[(rr+8)*33 + cc+1] = acc[mt][nt][3];
            }
    }
    __syncthreads();

    if (tid < 64){
        float s = red[0][tid] + red[1][tid] + red[2][tid] + red[3][tid];
        g_Csum[(chunk*BATCH + b)*64 + tid] = s;
    }

    if (khalf == 0){
        const float* sc2 = &Xs[0][0][0] + quad * 1056;
        const size_t base = (size_t)(chunk*BATCH + b) * 4096;
        #pragma unroll
        for (int mt = 0; mt < 2; mt++)
            #pragma unroll
            for (int nt = 0; nt < 4; nt++){
                int rr = mt*16 + lg;
                int cc = nt*8 + lc*2;
                int grow = m0 + rr, gcol = n0 + cc;
                g_Spart[base + (size_t)grow*64 + gcol]       = acc[mt][nt][0] + sc2[rr*33 + cc];
                g_Spart[base + (size_t)grow*64 + gcol + 1]   = acc[mt][nt][1] + sc2[rr*33 + cc + 1];
                g_Spart[base + (size_t)(grow+8)*64 + gcol]   = acc[mt][nt][2] + sc2[(rr+8)*33 + cc];
                g_Spart[base + (size_t)(grow+8)*64 + gcol+1] = acc[mt][nt][3] + sc2[(rr+8)*33 + cc+1];
            }
    }
}

/* ------------------------------------------------------------------ */
/* Kernel 2: reduce chunk partials, mean-correct, +lambda*I, extract
   upper-tri, bitonic-sort 4096 (pad INF) in smem, emit sorted run.    */
/* ------------------------------------------------------------------ */
__global__ __launch_bounds__(512) void finalize_sort(void){
    __shared__ float mu[64];
    __shared__ float s[4096];
    const int b = blockIdx.x;
    const int tid = threadIdx.x;

    if (tid < 64){
        float m = 0.f;
        #pragma unroll
        for (int c = 0; c < CHUNKS; c++) m += g_Csum[(c*BATCH + b)*64 + tid];
        mu[tid] = m * (1.f / (float)NROWS);
    }
    __syncthreads();

    for (int t = tid; t < 4096; t += 512){
        if (t < TRI){
            /* invert linear tri index -> (i, j), i <= j */
            int i = (int)((2.f*DDIM + 1.f - sqrtf((2.f*DDIM+1.f)*(2.f*DDIM+1.f) - 8.f*(float)t)) * 0.5f);
            if (i < 0) i = 0;
            if (i > DDIM-1) i = DDIM-1;
            while (i > 0 && (i*DDIM - (i*(i-1))/2) > t) i--;
            while (((i+1)*DDIM - ((i+1)*i)/2) <= t) i++;
            int off = i*DDIM - (i*(i-1))/2;
            int j = i + (t - off);

            float acc = 0.f;
            #pragma unroll
            for (int c = 0; c < CHUNKS; c++)
                acc += g_Spart[(size_t)(c*BATCH + b)*4096 + (size_t)i*64 + j];

            float cov = (acc - (float)NROWS * mu[i] * mu[j]) * (1.f / (float)(NROWS-1));
            if (i == j) cov += LAMBDA_REG;
            s[t] = cov;
        } else {
            s[t] = __int_as_float(0x7f800000);  /* +INF pad */
        }
    }
    __syncthreads();

    for (int k = 2; k <= 4096; k <<= 1){
        for (int j = k >> 1; j > 0; j >>= 1){
            for (int i = tid; i < 4096; i += 512){
                int ixj = i ^ j;
                if (ixj > i){
                    float a = s[i], c = s[ixj];
                    bool up = ((i & k) == 0);
                    if (up ? (a > c) : (a < c)){ s[i] = c; s[ixj] = a; }
                }
            }
            __syncthreads();
        }
    }
    for (int i = tid; i < TRI; i += 512) g_bufA[b*TRI + i] = s[i];
}

/* ------------------------------------------------------------------ */
/* Kernel 3: W-way merge round. Buffers selected DEVICE-side via mode
   (passing __device__ array symbols from host code is invalid!).      */
/* ------------------------------------------------------------------ */
template<int W, int LOGP>
__global__ __launch_bounds__(256) void merge_k(int L, int mode, float* final_out){
    const float* src; float* dst;
    if      (mode == 0){ src = g_bufA; dst = g_bufB; }
    else if (mode == 1){ src = g_bufB; dst = g_bufA; }
    else               { src = g_bufA; dst = final_out; }

    int gid = blockIdx.x * blockDim.x + threadIdx.x;
    if (gid >= TOTAL) return;

    int grpSz = W * L;
    int group = gid / grpSz;
    int base  = group * grpSz;
    int r     = (gid - base) / L;
    int local = gid - base - r * L;
    float v = src[gid];

    const float* run[W-1];
    bool useLE[W-1];
    int lo[W-1];
    int q = 0;
    #pragma unroll
    for (int sRun = 0; sRun < W; sRun++){
        if (sRun == r) continue;
        run[q]   = src + base + sRun * L;
        useLE[q] = (sRun < r);       /* earlier runs win ties */
        lo[q]    = 0;
        q++;
    }

    for (int step = (1 << LOGP); step >= 1; step >>= 1){
        #pragma unroll
        for (int p = 0; p < W-1; p++){
            int probe = lo[p] + step;
            if (probe <= L){
                float w = run[p][probe - 1];
                bool c = useLE[p] ? (w <= v) : (w < v);
                if (c) lo[p] = probe;
            }
        }
    }

    int rank = local;
    #pragma unroll
    for (int p = 0; p < W-1; p++) rank += lo[p];
    dst[base + rank] = v;
}

/* ------------------------------------------------------------------ */
extern "C" void kernel_launch(void* const* d_in, const int* in_sizes, int n_in,
                              void* d_out, int out_size){
    const float* x = (const float*)d_in[0];
    float* out = (float*)d_out;

    dim3 gcov(CHUNKS, BATCH);
    cov_partial<<<gcov, 256>>>(x);
    finalize_sort<<<BATCH, 512>>>();

    int mgrid = (TOTAL + 255) / 256;
    merge_k<4,12><<<mgrid, 256>>>(TRI,    0, out);  /* A: 32 runs -> B: 8 runs */
    merge_k<4,14><<<mgrid, 256>>>(TRI*4,  1, out);  /* B: 8 runs  -> A: 2 runs */
    merge_k<2,16><<<mgrid, 256>>>(TRI*16, 2, out);  /* A: 2 runs  -> d_out     */
}

// round 4
// speedup vs baseline: 1.5252x; 1.1816x over previous
#include <cuda_runtime.h>
#include <math.h>
#include <float.h>
#include <stdint.h>

#define BATCH 32
#define NROWS 16384
#define DDIM 64
#define CHUNKS 16
#define RPC (NROWS/CHUNKS)     /* 1024 rows per chunk */
#define NT (RPC/64)            /* 16 tiles of 64 rows */
#define TRI 2080
#define TOTAL (BATCH*TRI)      /* 66560 */
#define LAMBDA_REG 0.01f
#define SP 72                  /* smem row stride: 72 mod 32 = 8 -> conflict-free */

__device__ float g_Spart[CHUNKS*BATCH*DDIM*DDIM];  /* 8 MB partial Gram */
__device__ float g_Csum[CHUNKS*BATCH*DDIM];
__device__ float g_bufA[TOTAL];
__device__ float g_bufB[TOTAL];

__device__ __forceinline__ unsigned tf32r(float v){
    unsigned u;
    asm("cvt.rna.tf32.f32 %0, %1;" : "=r"(u) : "f"(v));
    return u;
}

__device__ __forceinline__ void mma8(float c[4],
                                     unsigned a0, unsigned a1, unsigned a2, unsigned a3,
                                     unsigned b0, unsigned b1){
    asm volatile("mma.sync.aligned.m16n8k8.row.col.f32.tf32.tf32.f32 "
        "{%0,%1,%2,%3},{%4,%5,%6,%7},{%8,%9},{%0,%1,%2,%3};"
        : "+f"(c[0]),"+f"(c[1]),"+f"(c[2]),"+f"(c[3])
        : "r"(a0),"r"(a1),"r"(a2),"r"(a3),"r"(b0),"r"(b1));
}

/* ------------------------------------------------------------------ */
/* Kernel 1: per-(chunk,batch) partial Gram via tf32 MMA.
   Register-staged LDG -> cvt.rna + colsum -> STS, double-buffered smem,
   ONE barrier per tile. 8 warps = 4 output quadrants x 2 k-halves.    */
/* ------------------------------------------------------------------ */
__global__ __launch_bounds__(256) void cov_partial(const float* __restrict__ x){
    __shared__ float Xs[2][64][SP];     /* 2 x 18432 B */
    __shared__ float red[16][64];

    const int chunk = blockIdx.x;
    const int b     = blockIdx.y;
    const int tid   = threadIdx.x;
    const int wid   = tid >> 5;
    const int lane  = tid & 31;
    const int khalf = wid >> 2;            /* 0/1: k-range 0-31 / 32-63 */
    const int quad  = wid & 3;             /* output quadrant           */
    const int m0 = (quad >> 1) * 32;
    const int n0 = (quad & 1) * 32;
    const int lg = lane >> 2;              /* 0..7 */
    const int lc = lane & 3;               /* 0..3 */

    float acc[2][4][4];
    #pragma unroll
    for (int mt = 0; mt < 2; mt++)
        #pragma unroll
        for (int nt = 0; nt < 4; nt++)
            #pragma unroll
            for (int v = 0; v < 4; v++) acc[mt][nt][v] = 0.f;

    /* staging: thread loads rows sr+16i, cols sc*4..sc*4+3 */
    const int sr = tid >> 4;               /* 0..15 */
    const int sc = tid & 15;               /* 0..15 */
    const float* xb = x + ((size_t)b * NROWS + (size_t)chunk * RPC) * DDIM;

    float4 regs[4];
    float cs0 = 0.f, cs1 = 0.f, cs2 = 0.f, cs3 = 0.f;

    /* prologue: tile 0 */
    {
        const float* src = xb;
        #pragma unroll
        for (int i = 0; i < 4; i++)
            regs[i] = *(const float4*)(src + (size_t)(sr + 16*i)*DDIM + sc*4);
        #pragma unroll
        for (int i = 0; i < 4; i++){
            int row = sr + 16*i;
            cs0 += regs[i].x; cs1 += regs[i].y; cs2 += regs[i].z; cs3 += regs[i].w;
            float4 w;
            w.x = __uint_as_float(tf32r(regs[i].x));
            w.y = __uint_as_float(tf32r(regs[i].y));
            w.z = __uint_as_float(tf32r(regs[i].z));
            w.w = __uint_as_float(tf32r(regs[i].w));
            *(float4*)&Xs[0][row][sc*4] = w;
        }
    }
    __syncthreads();

    for (int t = 0; t < NT; t++){
        const int cb = t & 1;

        /* issue next tile's LDGs early (latency hidden behind MMAs) */
        if (t + 1 < NT){
            const float* src = xb + (size_t)(t+1) * 64 * DDIM;
            #pragma unroll
            for (int i = 0; i < 4; i++)
                regs[i] = *(const float4*)(src + (size_t)(sr + 16*i)*DDIM + sc*4);
        }

        /* MMA over this warp's k-half */
        #pragma unroll
        for (int s = 0; s < 4; s++){
            const int kk = khalf*32 + s*8;
            unsigned a[2][4];
            #pragma unroll
            for (int mt = 0; mt < 2; mt++){
                int m = m0 + mt*16;
                a[mt][0] = __float_as_uint(Xs[cb][kk   + lc][m     + lg]);
                a[mt][1] = __float_as_uint(Xs[cb][kk   + lc][m + 8 + lg]);
                a[mt][2] = __float_as_uint(Xs[cb][kk+4 + lc][m     + lg]);
                a[mt][3] = __float_as_uint(Xs[cb][kk+4 + lc][m + 8 + lg]);
            }
            unsigned bf[4][2];
            #pragma unroll
            for (int nt = 0; nt < 4; nt++){
                int nb = n0 + nt*8;
                bf[nt][0] = __float_as_uint(Xs[cb][kk   + lc][nb + lg]);
                bf[nt][1] = __float_as_uint(Xs[cb][kk+4 + lc][nb + lg]);
            }
            #pragma unroll
            for (int mt = 0; mt < 2; mt++)
                #pragma unroll
                for (int nt = 0; nt < 4; nt++)
                    mma8(acc[mt][nt], a[mt][0], a[mt][1], a[mt][2], a[mt][3],
                         bf[nt][0], bf[nt][1]);
        }

        /* store next tile (cvt.rna + exact colsum from registers) */
        if (t + 1 < NT){
            const int nb = (t+1) & 1;
            #pragma unroll
            for (int i = 0; i < 4; i++){
                int row = sr + 16*i;
                cs0 += regs[i].x; cs1 += regs[i].y; cs2 += regs[i].z; cs3 += regs[i].w;
                float4 w;
                w.x = __uint_as_float(tf32r(regs[i].x));
                w.y = __uint_as_float(tf32r(regs[i].y));
                w.z = __uint_as_float(tf32r(regs[i].z));
                w.w = __uint_as_float(tf32r(regs[i].w));
                *(float4*)&Xs[nb][row][sc*4] = w;
            }
        }
        __syncthreads();
    }

    /* colsum partials -> red */
    red[sr][sc*4+0] = cs0;
    red[sr][sc*4+1] = cs1;
    red[sr][sc*4+2] = cs2;
    red[sr][sc*4+3] = cs3;

    /* k-half 1 warps spill accumulators into (now free) Xs buffer 0 */
    if (khalf == 1){
        float* sc2 = &Xs[0][0][0] + quad * 1056;   /* 32x33 padded */
        #pragma unroll
        for (int mt = 0; mt < 2; mt++)
            #pragma unroll
            for (int nt = 0; nt < 4; nt++){
                int rr = mt*16 + lg;
                int cc = nt*8 + lc*2;
                sc2[rr*33 + cc]       = acc[mt][nt][0];
                sc2[rr*33 + cc + 1]   = acc[mt][nt][1];
                sc2[(rr+8)*33 + cc]   = acc[mt][nt][2];
                sc2[(rr+8)*33 + cc+1] = acc[mt][nt][3];
            }
    }
    __syncthreads();

    if (tid < 64){
        float s = 0.f;
        #pragma unroll
        for (int q = 0; q < 16; q++) s += red[q][tid];
        g_Csum[(chunk*BATCH + b)*64 + tid] = s;
    }

    if (khalf == 0){
        const float* sc2 = &Xs[0][0][0] + quad * 1056;
        const size_t base = (size_t)(chunk*BATCH + b) * 4096;
        #pragma unroll
        for (int mt = 0; mt < 2; mt++)
            #pragma unroll
            for (int nt = 0; nt < 4; nt++){
                int rr = mt*16 + lg;
                int cc = nt*8 + lc*2;
                int grow = m0 + rr, gcol = n0 + cc;
                g_Spart[base + (size_t)grow*64 + gcol]       = acc[mt][nt][0] + sc2[rr*33 + cc];
                g_Spart[base + (size_t)grow*64 + gcol + 1]   = acc[mt][nt][1] + sc2[rr*33 + cc + 1];
                g_Spart[base + (size_t)(grow+8)*64 + gcol]   = acc[mt][nt][2] + sc2[(rr+8)*33 + cc];
                g_Spart[base + (size_t)(grow+8)*64 + gcol+1] = acc[mt][nt][3] + sc2[(rr+8)*33 + cc+1];
            }
    }
}

/* ------------------------------------------------------------------ */
/* Kernel 2: reduce chunk partials, mean-correct, +lambda*I, extract
   upper-tri, bitonic-sort 4096 (pad INF) in smem, emit sorted run.    */
/* ------------------------------------------------------------------ */
__global__ __launch_bounds__(1024) void finalize_sort(void){
    __shared__ float mu[64];
    __shared__ float s[4096];
    const int b = blockIdx.x;
    const int tid = threadIdx.x;

    if (tid < 64){
        float m = 0.f;
        #pragma unroll
        for (int c = 0; c < CHUNKS; c++) m += g_Csum[(c*BATCH + b)*64 + tid];
        mu[tid] = m * (1.f / (float)NROWS);
    }
    __syncthreads();

    for (int t = tid; t < 4096; t += 1024){
        if (t < TRI){
            /* invert linear tri index -> (i, j), i <= j */
            int i = (int)((2.f*DDIM + 1.f - sqrtf((2.f*DDIM+1.f)*(2.f*DDIM+1.f) - 8.f*(float)t)) * 0.5f);
            if (i < 0) i = 0;
            if (i > DDIM-1) i = DDIM-1;
            while (i > 0 && (i*DDIM - (i*(i-1))/2) > t) i--;
            while (((i+1)*DDIM - ((i+1)*i)/2) <= t) i++;
            int off = i*DDIM - (i*(i-1))/2;
            int j = i + (t - off);

            float acc = 0.f;
            #pragma unroll
            for (int c = 0; c < CHUNKS; c++)
                acc += g_Spart[(size_t)(c*BATCH + b)*4096 + (size_t)i*64 + j];

            float cov = (acc - (float)NROWS * mu[i] * mu[j]) * (1.f / (float)(NROWS-1));
            if (i == j) cov += LAMBDA_REG;
            s[t] = cov;
        } else {
            s[t] = __int_as_float(0x7f800000);  /* +INF pad */
        }
    }
    __syncthreads();

    for (int k = 2; k <= 4096; k <<= 1){
        for (int j = k >> 1; j > 0; j >>= 1){
            for (int i = tid; i < 4096; i += 1024){
                int ixj = i ^ j;
                if (ixj > i){
                    float a = s[i], c = s[ixj];
                    bool up = ((i & k) == 0);
                    if (up ? (a > c) : (a < c)){ s[i] = c; s[ixj] = a; }
                }
            }
            __syncthreads();
        }
    }
    for (int i = tid; i < TRI; i += 1024) g_bufA[b*TRI + i] = s[i];
}

/* ------------------------------------------------------------------ */
/* Kernel 3: W-way merge round. Each element finds its global rank via
   (W-1) interleaved branchless binary searches. Buffers selected
   DEVICE-side via mode.                                               */
/* ------------------------------------------------------------------ */
template<int W, int LOGP>
__global__ __launch_bounds__(256) void merge_k(int L, int mode, float* final_out){
    const float* src; float* dst;
    if (mode == 0){ src = g_bufA; dst = g_bufB; }
    else          { src = g_bufB; dst = final_out; }

    int gid = blockIdx.x * blockDim.x + threadIdx.x;
    if (gid >= TOTAL) return;

    int grpSz = W * L;
    int group = gid / grpSz;
    int base  = group * grpSz;
    int r     = (gid - base) / L;
    int local = gid - base - r * L;
    float v = src[gid];

    const float* run[W-1];
    bool useLE[W-1];
    int lo[W-1];
    int q = 0;
    #pragma unroll
    for (int sRun = 0; sRun < W; sRun++){
        if (sRun == r) continue;
        run[q]   = src + base + sRun * L;
        useLE[q] = (sRun < r);       /* earlier runs win ties */
        lo[q]    = 0;
        q++;
    }

    for (int step = (1 << LOGP); step >= 1; step >>= 1){
        #pragma unroll
        for (int p = 0; p < W-1; p++){
            int probe = lo[p] + step;
            if (probe <= L){
                float w = run[p][probe - 1];
                bool c = useLE[p] ? (w <= v) : (w < v);
                if (c) lo[p] = probe;
            }
        }
    }

    int rank = local;
    #pragma unroll
    for (int p = 0; p < W-1; p++) rank += lo[p];
    dst[base + rank] = v;
}

/* ------------------------------------------------------------------ */
extern "C" void kernel_launch(void* const* d_in, const int* in_sizes, int n_in,
                              void* d_out, int out_size){
    const float* x = (const float*)d_in[0];
    float* out = (float*)d_out;

    dim3 gcov(CHUNKS, BATCH);
    cov_partial<<<gcov, 256>>>(x);
    finalize_sort<<<BATCH, 1024>>>();

    int mgrid = (TOTAL + 255) / 256;
    merge_k<8,11><<<mgrid, 256>>>(TRI,   0, out);  /* A: 32 runs -> B: 4 runs */
    merge_k<4,14><<<mgrid, 256>>>(TRI*8, 1, out);  /* B: 4 runs  -> d_out     */
}

// round 5
// speedup vs baseline: 1.5555x; 1.0199x over previous
#include <cuda_runtime.h>
#include <math.h>
#include <float.h>
#include <stdint.h>

#define BATCH 32
#define NROWS 16384
#define DDIM 64
#define CHUNKS 8
#define RPC (NROWS/CHUNKS)     /* 2048 rows per chunk */
#define NT (RPC/64)            /* 32 tiles of 64 rows */
#define TRI 2080
#define TOTAL (BATCH*TRI)      /* 66560 */
#define LAMBDA_REG 0.01f
#define SP 72                  /* smem row stride: conflict-free for frag reads */

/* g_Spart: [chunk][batch][3 quadrants][32*32]  (q: 0=Q00, 1=Q11, 2=Q01) */
__device__ float g_Spart[CHUNKS*BATCH*3*1024];
__device__ float g_Csum[CHUNKS*BATCH*DDIM];
__device__ float g_bufA[TOTAL];
__device__ float g_bufB[TOTAL];

__device__ __forceinline__ unsigned tf32r(float v){
    unsigned u;
    asm("cvt.rna.tf32.f32 %0, %1;" : "=r"(u) : "f"(v));
    return u;
}

__device__ __forceinline__ void mma8(float c[4],
                                     unsigned a0, unsigned a1, unsigned a2, unsigned a3,
                                     unsigned b0, unsigned b1){
    asm volatile("mma.sync.aligned.m16n8k8.row.col.f32.tf32.tf32.f32 "
        "{%0,%1,%2,%3},{%4,%5,%6,%7},{%8,%9},{%0,%1,%2,%3};"
        : "+f"(c[0]),"+f"(c[1]),"+f"(c[2]),"+f"(c[3])
        : "r"(a0),"r"(a1),"r"(a2),"r"(a3),"r"(b0),"r"(b1));
}

/* ------------------------------------------------------------------ */
/* Kernel 1: partial Gram via tf32 MMA, symmetric (3 quadrants only). */
/* 8 warps: 0-1 Q00(khalf), 2-3 Q11(khalf), 4-7 Q01(kquarter).       */
/* Register-staged LDG -> cvt.rna + colsum -> STS, double-buffered.   */
/* ------------------------------------------------------------------ */
__global__ __launch_bounds__(256) void cov_partial(const float* __restrict__ x){
    __shared__ float Xs[2][64][SP];     /* 36 KB, also reused for epilogue */
    __shared__ float red[16][64];

    const int chunk = blockIdx.x;
    const int b     = blockIdx.y;
    const int tid   = threadIdx.x;
    const int wid   = tid >> 5;
    const int lane  = tid & 31;
    const int lg = lane >> 2;              /* 0..7 */
    const int lc = lane & 3;               /* 0..3 */

    int m0, n0, kbase;
    const bool diag = (wid < 4);
    if (wid < 2)      { m0 = 0;  n0 = 0;  kbase = wid * 32;       }  /* Q00 */
    else if (wid < 4) { m0 = 32; n0 = 32; kbase = (wid - 2) * 32; }  /* Q11 */
    else              { m0 = 0;  n0 = 32; kbase = (wid - 4) * 16; }  /* Q01 */

    float acc[2][4][4];
    #pragma unroll
    for (int mt = 0; mt < 2; mt++)
        #pragma unroll
        for (int nt = 0; nt < 4; nt++)
            #pragma unroll
            for (int v = 0; v < 4; v++) acc[mt][nt][v] = 0.f;

    const int sr = tid >> 4;               /* 0..15 */
    const int sc = tid & 15;               /* 0..15 */
    const float* xb = x + ((size_t)b * NROWS + (size_t)chunk * RPC) * DDIM;

    float4 regs[4];
    float cs0 = 0.f, cs1 = 0.f, cs2 = 0.f, cs3 = 0.f;

    /* prologue: tile 0 */
    {
        #pragma unroll
        for (int i = 0; i < 4; i++)
            regs[i] = *(const float4*)(xb + (size_t)(sr + 16*i)*DDIM + sc*4);
        #pragma unroll
        for (int i = 0; i < 4; i++){
            int row = sr + 16*i;
            cs0 += regs[i].x; cs1 += regs[i].y; cs2 += regs[i].z; cs3 += regs[i].w;
            float4 w;
            w.x = __uint_as_float(tf32r(regs[i].x));
            w.y = __uint_as_float(tf32r(regs[i].y));
            w.z = __uint_as_float(tf32r(regs[i].z));
            w.w = __uint_as_float(tf32r(regs[i].w));
            *(float4*)&Xs[0][row][sc*4] = w;
        }
    }
    __syncthreads();

    for (int t = 0; t < NT; t++){
        const int cb = t & 1;

        if (t + 1 < NT){
            const float* src = xb + (size_t)(t+1) * 64 * DDIM;
            #pragma unroll
            for (int i = 0; i < 4; i++)
                regs[i] = *(const float4*)(src + (size_t)(sr + 16*i)*DDIM + sc*4);
        }

        /* MMA over this warp's k-range */
        #define DO_STEP(S_)                                                     \
        {                                                                       \
            const int kk = kbase + (S_)*8;                                      \
            unsigned a[2][4];                                                   \
            _Pragma("unroll")                                                   \
            for (int mt = 0; mt < 2; mt++){                                     \
                int m = m0 + mt*16;                                             \
                a[mt][0] = __float_as_uint(Xs[cb][kk   + lc][m     + lg]);      \
                a[mt][1] = __float_as_uint(Xs[cb][kk   + lc][m + 8 + lg]);      \
                a[mt][2] = __float_as_uint(Xs[cb][kk+4 + lc][m     + lg]);      \
                a[mt][3] = __float_as_uint(Xs[cb][kk+4 + lc][m + 8 + lg]);      \
            }                                                                   \
            unsigned bf[4][2];                                                  \
            _Pragma("unroll")                                                   \
            for (int nt = 0; nt < 4; nt++){                                     \
                int nb2 = n0 + nt*8;                                            \
                bf[nt][0] = __float_as_uint(Xs[cb][kk   + lc][nb2 + lg]);       \
                bf[nt][1] = __float_as_uint(Xs[cb][kk+4 + lc][nb2 + lg]);       \
            }                                                                   \
            _Pragma("unroll")                                                   \
            for (int mt = 0; mt < 2; mt++)                                      \
                _Pragma("unroll")                                               \
                for (int nt = 0; nt < 4; nt++)                                  \
                    mma8(acc[mt][nt], a[mt][0], a[mt][1], a[mt][2], a[mt][3],   \
                         bf[nt][0], bf[nt][1]);                                 \
        }

        if (diag){
            DO_STEP(0) DO_STEP(1) DO_STEP(2) DO_STEP(3)
        } else {
            DO_STEP(0) DO_STEP(1)
        }
        #undef DO_STEP

        /* store next tile (cvt.rna + exact colsum from registers) */
        if (t + 1 < NT){
            const int nb = (t+1) & 1;
            #pragma unroll
            for (int i = 0; i < 4; i++){
                int row = sr + 16*i;
                cs0 += regs[i].x; cs1 += regs[i].y; cs2 += regs[i].z; cs3 += regs[i].w;
                float4 w;
                w.x = __uint_as_float(tf32r(regs[i].x));
                w.y = __uint_as_float(tf32r(regs[i].y));
                w.z = __uint_as_float(tf32r(regs[i].z));
                w.w = __uint_as_float(tf32r(regs[i].w));
                *(float4*)&Xs[nb][row][sc*4] = w;
            }
        }
        __syncthreads();
    }

    /* colsum partials */
    red[sr][sc*4+0] = cs0;
    red[sr][sc*4+1] = cs1;
    red[sr][sc*4+2] = cs2;
    red[sr][sc*4+3] = cs3;

    /* partial-accumulator spill: warps 1,3,5,6,7 -> smem (reuse Xs)
       slots: w1->0, w3->1, w5->2, w6->3, w7->4 (each 32x33 padded)    */
    float* sbase = &Xs[0][0][0];
    int slot = -1;
    if (wid == 1) slot = 0;
    else if (wid == 3) slot = 1;
    else if (wid >= 5) slot = wid - 3;   /* 5->2, 6->3, 7->4 */
    if (slot >= 0){
        float* sc2 = sbase + slot * 1056;
        #pragma unroll
        for (int mt = 0; mt < 2; mt++)
            #pragma unroll
            for (int nt = 0; nt < 4; nt++){
                int rr = mt*16 + lg;
                int cc = nt*8 + lc*2;
                sc2[rr*33 + cc]       = acc[mt][nt][0];
                sc2[rr*33 + cc + 1]   = acc[mt][nt][1];
                sc2[(rr+8)*33 + cc]   = acc[mt][nt][2];
                sc2[(rr+8)*33 + cc+1] = acc[mt][nt][3];
            }
    }
    __syncthreads();

    if (tid < 64){
        float s = 0.f;
        #pragma unroll
        for (int q = 0; q < 16; q++) s += red[q][tid];
        g_Csum[(chunk*BATCH + b)*64 + tid] = s;
    }

    /* reducers: warp0 (Q00, +slot0), warp2 (Q11, +slot1),
                 warp4 (Q01, +slots 2,3,4) -> gmem quadrant store      */
    if (wid == 0 || wid == 2 || wid == 4){
        const int q = (wid == 0) ? 0 : (wid == 2) ? 1 : 2;
        const size_t base = ((size_t)(chunk*BATCH + b) * 3 + q) * 1024;
        const float* p0 = sbase + ((wid == 0) ? 0 : (wid == 2) ? 1 : 2) * 1056;
        const float* p1 = (wid == 4) ? sbase + 3*1056 : 0;
        const float* p2 = (wid == 4) ? sbase + 4*1056 : 0;
        #pragma unroll
        for (int mt = 0; mt < 2; mt++)
            #pragma unroll
            for (int nt = 0; nt < 4; nt++){
                int rr = mt*16 + lg;
                int cc = nt*8 + lc*2;
                float v0 = acc[mt][nt][0] + p0[rr*33 + cc];
                float v1 = acc[mt][nt][1] + p0[rr*33 + cc + 1];
                float v2 = acc[mt][nt][2] + p0[(rr+8)*33 + cc];
                float v3 = acc[mt][nt][3] + p0[(rr+8)*33 + cc+1];
                if (wid == 4){
                    v0 += p1[rr*33 + cc]     + p2[rr*33 + cc];
                    v1 += p1[rr*33 + cc + 1] + p2[rr*33 + cc + 1];
                    v2 += p1[(rr+8)*33 + cc]   + p2[(rr+8)*33 + cc];
                    v3 += p1[(rr+8)*33 + cc+1] + p2[(rr+8)*33 + cc+1];
                }
                g_Spart[base + (size_t)rr*32 + cc]       = v0;
                g_Spart[base + (size_t)rr*32 + cc + 1]   = v1;
                g_Spart[base + (size_t)(rr+8)*32 + cc]   = v2;
                g_Spart[base + (size_t)(rr+8)*32 + cc+1] = v3;
            }
    }
}

/* ------------------------------------------------------------------ */
/* Kernel 2: reduce chunk partials, mean-correct, +lambda*I, extract
   upper-tri, bitonic-sort 4096 (pad INF) in smem, emit sorted run.    */
/* ------------------------------------------------------------------ */
__global__ __launch_bounds__(1024) void finalize_sort(void){
    __shared__ float mu[64];
    __shared__ float s[4096];
    const int b = blockIdx.x;
    const int tid = threadIdx.x;

    if (tid < 64){
        float m = 0.f;
        #pragma unroll
        for (int c = 0; c < CHUNKS; c++) m += g_Csum[(c*BATCH + b)*64 + tid];
        mu[tid] = m * (1.f / (float)NROWS);
    }
    __syncthreads();

    for (int t = tid; t < 4096; t += 1024){
        if (t < TRI){
            /* invert linear tri index -> (i, j), i <= j */
            int i = (int)((2.f*DDIM + 1.f - sqrtf((2.f*DDIM+1.f)*(2.f*DDIM+1.f) - 8.f*(float)t)) * 0.5f);
            if (i < 0) i = 0;
            if (i > DDIM-1) i = DDIM-1;
            while (i > 0 && (i*DDIM - (i*(i-1))/2) > t) i--;
            while (((i+1)*DDIM - ((i+1)*i)/2) <= t) i++;
            int off = i*DDIM - (i*(i-1))/2;
            int j = i + (t - off);

            /* quadrant mapping */
            int q, r, c2;
            if (j < 32)       { q = 0; r = i;      c2 = j;      }
            else if (i >= 32) { q = 1; r = i - 32; c2 = j - 32; }
            else              { q = 2; r = i;      c2 = j - 32; }

            float acc = 0.f;
            #pragma unroll
            for (int c = 0; c < CHUNKS; c++)
                acc += g_Spart[((size_t)(c*BATCH + b)*3 + q)*1024 + (size_t)r*32 + c2];

            float cov = (acc - (float)NROWS * mu[i] * mu[j]) * (1.f / (float)(NROWS-1));
            if (i == j) cov += LAMBDA_REG;
            s[t] = cov;
        } else {
            s[t] = __int_as_float(0x7f800000);  /* +INF pad */
        }
    }
    __syncthreads();

    for (int k = 2; k <= 4096; k <<= 1){
        for (int j = k >> 1; j > 0; j >>= 1){
            for (int i = tid; i < 4096; i += 1024){
                int ixj = i ^ j;
                if (ixj > i){
                    float a = s[i], c = s[ixj];
                    bool up = ((i & k) == 0);
                    if (up ? (a > c) : (a < c)){ s[i] = c; s[ixj] = a; }
                }
            }
            __syncthreads();
        }
    }
    for (int i = tid; i < TRI; i += 1024) g_bufA[b*TRI + i] = s[i];
}

/* ------------------------------------------------------------------ */
/* Kernel 3: W-way merge round via (W-1) interleaved binary searches.  */
/* ------------------------------------------------------------------ */
template<int W, int LOGP>
__global__ __launch_bounds__(256) void merge_k(int L, int mode, float* final_out){
    const float* src; float* dst;
    if (mode == 0){ src = g_bufA; dst = g_bufB; }
    else          { src = g_bufB; dst = final_out; }

    int gid = blockIdx.x * blockDim.x + threadIdx.x;
    if (gid >= TOTAL) return;

    int grpSz = W * L;
    int group = gid / grpSz;
    int base  = group * grpSz;
    int r     = (gid - base) / L;
    int local = gid - base - r * L;
    float v = src[gid];

    const float* run[W-1];
    bool useLE[W-1];
    int lo[W-1];
    int q = 0;
    #pragma unroll
    for (int sRun = 0; sRun < W; sRun++){
        if (sRun == r) continue;
        run[q]   = src + base + sRun * L;
        useLE[q] = (sRun < r);       /* earlier runs win ties */
        lo[q]    = 0;
        q++;
    }

    for (int step = (1 << LOGP); step >= 1; step >>= 1){
        #pragma unroll
        for (int p = 0; p < W-1; p++){
            int probe = lo[p] + step;
            if (probe <= L){
                float w = run[p][probe - 1];
                bool c = useLE[p] ? (w <= v) : (w < v);
                if (c) lo[p] = probe;
            }
        }
    }

    int rank = local;
    #pragma unroll
    for (int p = 0; p < W-1; p++) rank += lo[p];
    dst[base + rank] = v;
}

/* ------------------------------------------------------------------ */
extern "C" void kernel_launch(void* const* d_in, const int* in_sizes, int n_in,
                              void* d_out, int out_size){
    const float* x = (const float*)d_in[0];
    float* out = (float*)d_out;

    dim3 gcov(CHUNKS, BATCH);
    cov_partial<<<gcov, 256>>>(x);
    finalize_sort<<<BATCH, 1024>>>();

    int mgrid = (TOTAL + 255) / 256;
    merge_k<8,11><<<mgrid, 256>>>(TRI,   0, out);  /* A: 32 runs -> B: 4 runs */
    merge_k<4,14><<<mgrid, 256>>>(TRI*8, 1, out);  /* B: 4 runs  -> d_out     */
}